// round 6
// baseline (speedup 1.0000x reference)
#include <cuda_runtime.h>
#include <cstdint>
#include <cstddef>

// Problem constants (fixed by the dataset)
#define B_TOT 4096
#define C_IN  512
#define O_TOT 1024
#define DD    10
#define LL    1024

// Tiling
#define OT        8                  // o's per CTA (one per warp)
#define NB        8                  // b-splits -> grid (8, 128)
#define B_PER_CTA (B_TOT / NB)       // 512 b's per CTA
#define NTHREADS  256
#define ST_PITCH  9                  // stage pitch: 9*lane+warp -> permutation banks
#define W_SM_FLOATS (OT * LL)        // 8192 floats = 32KB staged weights
#define SMEM_FLOATS (W_SM_FLOATS + 2 * 64 * ST_PITCH)
#define SMEM_BYTES  (SMEM_FLOATS * 4)

// Scratch: transposed x (xt[c][b]) so per-warp gathers are coalesced 128B lines.
__device__ float g_xt[(size_t)C_IN * B_TOT];
// Repacked thresholds / ordinals (ordinals pre-scaled by B_TOT)
__device__ float4 g_thp[O_TOT * 3];
__device__ int4   g_ordp[O_TOT * 3];

#define TRANS_BLOCKS ((C_IN / 32) * (B_TOT / 32))   // 16*128 = 2048
#define CONV_BLOCKS  48                             // 48*256 = 12288 = O_TOT*12

// Merged prologue: [0,2048) transpose x -> g_xt ; [2048,2096) repack params.
__global__ void prep_kernel(const float* __restrict__ x,
                            const float* __restrict__ th,
                            const void*  __restrict__ ord_raw) {
    if (blockIdx.x < TRANS_BLOCKS) {
        __shared__ float t[32][33];
        const int tb = blockIdx.x;
        const int cb = tb & (C_IN / 32 - 1);   // channel tile 0..15
        const int bb = tb >> 4;                // b tile 0..127
        const int lane = threadIdx.x & 31, w = threadIdx.x >> 5;
        #pragma unroll
        for (int r = w; r < 32; r += 8)
            t[r][lane] = x[(size_t)(bb * 32 + r) * C_IN + cb * 32 + lane];
        __syncthreads();
        #pragma unroll
        for (int r = w; r < 32; r += 8)
            g_xt[(size_t)(cb * 32 + r) * B_TOT + bb * 32 + lane] = t[lane][r];
    } else {
        // Detect ordinals dtype (int64 vs int32) by value-range test.
        __shared__ int is64_s;
        if (threadIdx.x == 0) {
            const long long* p = (const long long*)ord_raw;
            int ok = 1;
            for (int i = 0; i < 16; i++) {
                long long v = p[i];
                if (v < 0 || v >= C_IN) ok = 0;
            }
            is64_s = ok;
        }
        __syncthreads();
        const int use64 = is64_s;
        const long long* p64 = (const long long*)ord_raw;
        const int*       p32 = (const int*)ord_raw;
        float* thf = (float*)g_thp;
        int*   odf = (int*)g_ordp;
        int j = (blockIdx.x - TRANS_BLOCKS) * blockDim.x + threadIdx.x;
        if (j < O_TOT * 12) {
            int o = j / 12, k = j % 12;
            float tv = 0.0f;
            int   ov = 0;
            if (k < DD) {
                tv = th[o * DD + k];
                ov = (use64 ? (int)p64[o * DD + k] : p32[o * DD + k]) * B_TOT;
            }
            thf[j] = tv;
            odf[j] = ov;
        }
    }
}

__global__ __launch_bounds__(NTHREADS, 6)
void fern_kernel(const float* __restrict__ wts, float* __restrict__ out) {
    extern __shared__ float sm[];
    float* wsm   = sm;                  // [OT][LL] staged weights (32KB)
    float* stage = sm + W_SM_FLOATS;    // [2][64][ST_PITCH] ping-pong stage

    const int tid  = threadIdx.x;
    const int lane = tid & 31;          // b within tile
    const int warp = tid >> 5;          // o within CTA (fixed)
    const int o_begin = blockIdx.y * OT;
    const int bbase   = blockIdx.x * B_PER_CTA;

    // Stage weights [o_begin : o_begin+8] into smem. 2048 float4 / 256 thr = 8 each.
    {
        const float4* src = (const float4*)(wts + (size_t)o_begin * LL);
        float4* dst = (float4*)wsm;
        #pragma unroll
        for (int i = 0; i < W_SM_FLOATS / 4 / NTHREADS; i++)
            dst[tid + i * NTHREADS] = src[tid + i * NTHREADS];
    }

    // Per-warp params, loaded ONCE (o fixed for entire CTA lifetime).
    const int o = o_begin + warp;
    const float4 t0 = g_thp[o * 3 + 0];
    const float4 t1 = g_thp[o * 3 + 1];
    const float4 t2 = g_thp[o * 3 + 2];
    const int4   c0 = g_ordp[o * 3 + 0];
    const int4   c1 = g_ordp[o * 3 + 1];
    const int4   c2 = g_ordp[o * 3 + 2];

    // 10 base pointers: gathers become LDG [Rp + imm] on coalesced 128B lines.
    const float* xb  = g_xt + bbase + lane;
    const float* xp0 = xb + c0.x;  const float* xp1 = xb + c0.y;
    const float* xp2 = xb + c0.z;  const float* xp3 = xb + c0.w;
    const float* xp4 = xb + c1.x;  const float* xp5 = xb + c1.y;
    const float* xp6 = xb + c1.z;  const float* xp7 = xb + c1.w;
    const float* xp8 = xb + c2.x;  const float* xp9 = xb + c2.y;
    const float* wrow = wsm + (warp << 10);

    __syncthreads();   // weights staged

    #pragma unroll
    for (int itp = 0; itp < B_PER_CTA / 64; itp++) {     // 8 iterations
        float* sbuf = stage + (itp & 1) * (64 * ST_PITCH);
        #pragma unroll
        for (int half = 0; half < 2; half++) {
            const int off = itp * 64 + half * 32;        // compile-time constant
            // 10 independent coalesced LDGs (L1/L2-resident) in flight.
            float m0 = xp0[off] - t0.x;
            float m1 = xp1[off] - t0.y;
            float m2 = xp2[off] - t0.z;
            float m3 = xp3[off] - t0.w;
            float m4 = xp4[off] - t1.x;
            float m5 = xp5[off] - t1.y;
            float m6 = xp6[off] - t1.z;
            float m7 = xp7[off] - t1.w;
            float m8 = xp8[off] - t2.x;
            float m9 = xp9[off] - t2.y;

            int leaf = ((m0 > 0.0f) << 9) | ((m1 > 0.0f) << 8) |
                       ((m2 > 0.0f) << 7) | ((m3 > 0.0f) << 6) |
                       ((m4 > 0.0f) << 5) | ((m5 > 0.0f) << 4) |
                       ((m6 > 0.0f) << 3) | ((m7 > 0.0f) << 2) |
                       ((m8 > 0.0f) << 1) |  (m9 > 0.0f);

            // Balanced min tree (exact, order-independent).
            float mn = fminf(
                fminf(fminf(fminf(fabsf(m0), fabsf(m1)), fminf(fabsf(m2), fabsf(m3))),
                      fminf(fminf(fabsf(m4), fabsf(m5)), fminf(fabsf(m6), fabsf(m7)))),
                fminf(fabsf(m8), fabsf(m9)));

            // Divergent gather hits SMEM (random banks, ~3.4 avg wavefronts).
            float r = wrow[leaf] * mn;
            sbuf[(half * 32 + lane) * ST_PITCH + warp] = r;
        }
        __syncthreads();
        // Flush 64 b-rows x 8 o's; each thread 2 elements, 32B coalesced segments.
        // Ping-pong: no second barrier needed — next STS targets the other buffer,
        // and the following barrier (next iteration) fences reuse of this one.
        {
            const int bl = tid >> 3, oo = tid & 7;       // bl 0..31, oo 0..7
            const int bg = bbase + itp * 64;
            out[(size_t)(bg + bl) * O_TOT + o_begin + oo] =
                sbuf[bl * ST_PITCH + oo];
            out[(size_t)(bg + bl + 32) * O_TOT + o_begin + oo] =
                sbuf[(bl + 32) * ST_PITCH + oo];
        }
    }
}

extern "C" void kernel_launch(void* const* d_in, const int* in_sizes, int n_in,
                              void* d_out, int out_size) {
    (void)in_sizes; (void)n_in; (void)out_size;
    const float* x   = (const float*)d_in[0];
    const float* th  = (const float*)d_in[1];
    const void*  ord = d_in[2];
    const float* wts = (const float*)d_in[3];
    float* out = (float*)d_out;

    prep_kernel<<<TRANS_BLOCKS + CONV_BLOCKS, 256>>>(x, th, ord);

    cudaFuncSetAttribute(fern_kernel,
                         cudaFuncAttributeMaxDynamicSharedMemorySize, SMEM_BYTES);
    dim3 grid(NB, O_TOT / OT);   // (8, 128)
    fern_kernel<<<grid, NTHREADS, SMEM_BYTES>>>(wts, out);
}

// round 7
// speedup vs baseline: 1.9365x; 1.9365x over previous
#include <cuda_runtime.h>
#include <cstdint>
#include <cstddef>

// Problem constants (fixed by the dataset)
#define B_TOT 4096
#define C_IN  512
#define O_TOT 1024
#define DD    10
#define LL    1024

// Tiling
#define OT        16                 // o's per CTA (one per warp)
#define NB        8                  // b-splits -> grid (8, 64)
#define B_PER_CTA (B_TOT / NB)       // 512 b's per CTA
#define NTHREADS  512
#define ST_PITCH  66                 // stage [o][64 b] pitch: STS.64 + flush LDS conflict-free
#define W_SM_FLOATS (OT * LL)        // 16384 floats = 64KB staged weights
#define SMEM_FLOATS (W_SM_FLOATS + 2 * OT * ST_PITCH)
#define SMEM_BYTES  (SMEM_FLOATS * 4)

// Scratch: transposed x (xt[c][b]) so per-warp gathers are coalesced lines.
__device__ float g_xt[(size_t)C_IN * B_TOT];
// Repacked thresholds / ordinals (ordinals pre-scaled by B_TOT)
__device__ float4 g_thp[O_TOT * 3];
__device__ int4   g_ordp[O_TOT * 3];

#define TRANS_BLOCKS ((C_IN / 32) * (B_TOT / 32))   // 16*128 = 2048
#define CONV_BLOCKS  48                             // 48*256 = 12288 = O_TOT*12

// Merged prologue: [0,2048) transpose x -> g_xt ; [2048,2096) repack params.
__global__ void prep_kernel(const float* __restrict__ x,
                            const float* __restrict__ th,
                            const void*  __restrict__ ord_raw) {
    if (blockIdx.x < TRANS_BLOCKS) {
        __shared__ float t[32][33];
        const int tb = blockIdx.x;
        const int cb = tb & (C_IN / 32 - 1);   // channel tile 0..15
        const int bb = tb >> 4;                // b tile 0..127
        const int lane = threadIdx.x & 31, w = threadIdx.x >> 5;
        #pragma unroll
        for (int r = w; r < 32; r += 8)
            t[r][lane] = x[(size_t)(bb * 32 + r) * C_IN + cb * 32 + lane];
        __syncthreads();
        #pragma unroll
        for (int r = w; r < 32; r += 8)
            g_xt[(size_t)(cb * 32 + r) * B_TOT + bb * 32 + lane] = t[lane][r];
    } else {
        // Detect ordinals dtype (int64 vs int32) by value-range test.
        __shared__ int is64_s;
        if (threadIdx.x == 0) {
            const long long* p = (const long long*)ord_raw;
            int ok = 1;
            for (int i = 0; i < 16; i++) {
                long long v = p[i];
                if (v < 0 || v >= C_IN) ok = 0;
            }
            is64_s = ok;
        }
        __syncthreads();
        const int use64 = is64_s;
        const long long* p64 = (const long long*)ord_raw;
        const int*       p32 = (const int*)ord_raw;
        float* thf = (float*)g_thp;
        int*   odf = (int*)g_ordp;
        int j = (blockIdx.x - TRANS_BLOCKS) * blockDim.x + threadIdx.x;
        if (j < O_TOT * 12) {
            int o = j / 12, k = j % 12;
            float tv = 0.0f;
            int   ov = 0;
            if (k < DD) {
                tv = th[o * DD + k];
                ov = (use64 ? (int)p64[o * DD + k] : p32[o * DD + k]) * B_TOT;
            }
            thf[j] = tv;
            odf[j] = ov;
        }
    }
}

__global__ __launch_bounds__(NTHREADS, 2)
void fern_kernel(const float* __restrict__ wts, float* __restrict__ out) {
    extern __shared__ float sm[];
    float* wsm   = sm;                  // [OT][LL] staged weights (64KB)
    float* stage = sm + W_SM_FLOATS;    // [2][OT][ST_PITCH] ping-pong stage

    const int tid  = threadIdx.x;
    const int lane = tid & 31;
    const int warp = tid >> 5;          // o within CTA (fixed)
    const int o_begin = blockIdx.y * OT;
    const int bbase   = blockIdx.x * B_PER_CTA;

    // Stage weights [o_begin : o_begin+16] into smem. 4096 float4 / 512 thr = 8 each.
    {
        const float4* src = (const float4*)(wts + (size_t)o_begin * LL);
        float4* dst = (float4*)wsm;
        #pragma unroll
        for (int i = 0; i < W_SM_FLOATS / 4 / NTHREADS; i++)
            dst[tid + i * NTHREADS] = src[tid + i * NTHREADS];
    }

    // Per-warp params, loaded ONCE (o fixed for entire CTA lifetime).
    const int o = o_begin + warp;
    const float4 t0 = g_thp[o * 3 + 0];
    const float4 t1 = g_thp[o * 3 + 1];
    const float4 t2 = g_thp[o * 3 + 2];
    const int4   c0 = g_ordp[o * 3 + 0];
    const int4   c1 = g_ordp[o * 3 + 1];
    const int4   c2 = g_ordp[o * 3 + 2];

    // 10 float2 base pointers: each lane covers b = 2*lane, 2*lane+1.
    // (bbase and pre-scaled ordinals are even -> float2-aligned.)
    const float* xf = g_xt + bbase;
    const float2* xp0 = (const float2*)(xf + c0.x) + lane;
    const float2* xp1 = (const float2*)(xf + c0.y) + lane;
    const float2* xp2 = (const float2*)(xf + c0.z) + lane;
    const float2* xp3 = (const float2*)(xf + c0.w) + lane;
    const float2* xp4 = (const float2*)(xf + c1.x) + lane;
    const float2* xp5 = (const float2*)(xf + c1.y) + lane;
    const float2* xp6 = (const float2*)(xf + c1.z) + lane;
    const float2* xp7 = (const float2*)(xf + c1.w) + lane;
    const float2* xp8 = (const float2*)(xf + c2.x) + lane;
    const float2* xp9 = (const float2*)(xf + c2.y) + lane;
    const float* wrow = wsm + (warp << 10);

    __syncthreads();   // weights staged

    #pragma unroll
    for (int itp = 0; itp < B_PER_CTA / 64; itp++) {     // 8 iterations
        float* sbuf = stage + (itp & 1) * (OT * ST_PITCH);
        const int off = itp * 32;                        // float2 elements

        // 10 independent coalesced LDG.64 in flight (64 b's this iter).
        float2 v0 = xp0[off];
        float2 v1 = xp1[off];
        float2 v2 = xp2[off];
        float2 v3 = xp3[off];
        float2 v4 = xp4[off];
        float2 v5 = xp5[off];
        float2 v6 = xp6[off];
        float2 v7 = xp7[off];
        float2 v8 = xp8[off];
        float2 v9 = xp9[off];

        float r0, r1;
        {   // b = 2*lane  (.x components)
            float m0 = v0.x - t0.x, m1 = v1.x - t0.y, m2 = v2.x - t0.z;
            float m3 = v3.x - t0.w, m4 = v4.x - t1.x, m5 = v5.x - t1.y;
            float m6 = v6.x - t1.z, m7 = v7.x - t1.w, m8 = v8.x - t2.x;
            float m9 = v9.x - t2.y;
            int leaf = ((m0 > 0.0f) << 9) | ((m1 > 0.0f) << 8) |
                       ((m2 > 0.0f) << 7) | ((m3 > 0.0f) << 6) |
                       ((m4 > 0.0f) << 5) | ((m5 > 0.0f) << 4) |
                       ((m6 > 0.0f) << 3) | ((m7 > 0.0f) << 2) |
                       ((m8 > 0.0f) << 1) |  (m9 > 0.0f);
            float mn = fminf(
                fminf(fminf(fminf(fabsf(m0), fabsf(m1)), fminf(fabsf(m2), fabsf(m3))),
                      fminf(fminf(fabsf(m4), fabsf(m5)), fminf(fabsf(m6), fabsf(m7)))),
                fminf(fabsf(m8), fabsf(m9)));
            r0 = wrow[leaf] * mn;
        }
        {   // b = 2*lane + 1  (.y components)
            float m0 = v0.y - t0.x, m1 = v1.y - t0.y, m2 = v2.y - t0.z;
            float m3 = v3.y - t0.w, m4 = v4.y - t1.x, m5 = v5.y - t1.y;
            float m6 = v6.y - t1.z, m7 = v7.y - t1.w, m8 = v8.y - t2.x;
            float m9 = v9.y - t2.y;
            int leaf = ((m0 > 0.0f) << 9) | ((m1 > 0.0f) << 8) |
                       ((m2 > 0.0f) << 7) | ((m3 > 0.0f) << 6) |
                       ((m4 > 0.0f) << 5) | ((m5 > 0.0f) << 4) |
                       ((m6 > 0.0f) << 3) | ((m7 > 0.0f) << 2) |
                       ((m8 > 0.0f) << 1) |  (m9 > 0.0f);
            float mn = fminf(
                fminf(fminf(fminf(fabsf(m0), fabsf(m1)), fminf(fabsf(m2), fabsf(m3))),
                      fminf(fminf(fabsf(m4), fabsf(m5)), fminf(fabsf(m6), fabsf(m7)))),
                fminf(fabsf(m8), fabsf(m9)));
            r1 = wrow[leaf] * mn;
        }

        // Stage [o][b]: STS.64 consecutive -> conflict-free.
        *(float2*)&sbuf[warp * ST_PITCH + 2 * lane] = make_float2(r0, r1);
        __syncthreads();

        // Flush 64 b x 16 o. lanes 0-15: bl=2w, oo=0..15 -> 64B STG segments.
        // LDS banks (2*oo + bl)%32: even set / odd set per half-warp -> conflict-free.
        {
            const int bl = tid >> 4, oo = tid & 15;
            const int bg = bbase + itp * 64;
            out[(size_t)(bg + bl) * O_TOT + o_begin + oo] =
                sbuf[oo * ST_PITCH + bl];
            out[(size_t)(bg + bl + 32) * O_TOT + o_begin + oo] =
                sbuf[oo * ST_PITCH + bl + 32];
        }
        // Ping-pong: next iteration writes the other buffer; the next barrier
        // orders reuse of this one. No second barrier needed.
    }
}

extern "C" void kernel_launch(void* const* d_in, const int* in_sizes, int n_in,
                              void* d_out, int out_size) {
    (void)in_sizes; (void)n_in; (void)out_size;
    const float* x   = (const float*)d_in[0];
    const float* th  = (const float*)d_in[1];
    const void*  ord = d_in[2];
    const float* wts = (const float*)d_in[3];
    float* out = (float*)d_out;

    prep_kernel<<<TRANS_BLOCKS + CONV_BLOCKS, 256>>>(x, th, ord);

    cudaFuncSetAttribute(fern_kernel,
                         cudaFuncAttributeMaxDynamicSharedMemorySize, SMEM_BYTES);
    dim3 grid(NB, O_TOT / OT);   // (8, 64)
    fern_kernel<<<grid, NTHREADS, SMEM_BYTES>>>(wts, out);
}

// round 8
// speedup vs baseline: 2.0626x; 1.0651x over previous
#include <cuda_runtime.h>
#include <cstdint>
#include <cstddef>

// Problem constants (fixed by the dataset)
#define B_TOT 4096
#define C_IN  512
#define O_TOT 1024
#define DD    10
#define LL    1024

// Tiling
#define OT        8                  // o's per CTA (one per warp)
#define NB        8                  // b-splits -> grid (8, 128)
#define B_PER_CTA (B_TOT / NB)       // 512 b's per CTA
#define NTHREADS  256
#define ST_PITCH  68                 // stage [o][64 b] pitch: STS.64 + flush LDS conflict-free
#define W_SM_FLOATS (OT * LL)        // 8192 floats = 32KB staged weights
#define SMEM_FLOATS (W_SM_FLOATS + 2 * OT * ST_PITCH)
#define SMEM_BYTES  (SMEM_FLOATS * 4)

// Scratch: transposed x (xt[c][b]) so per-warp gathers are coalesced lines.
__device__ float g_xt[(size_t)C_IN * B_TOT];
// Repacked thresholds / ordinals (ordinals pre-scaled by B_TOT)
__device__ float4 g_thp[O_TOT * 3];
__device__ int4   g_ordp[O_TOT * 3];

#define TRANS_BLOCKS ((C_IN / 32) * (B_TOT / 32))   // 16*128 = 2048
#define CONV_BLOCKS  48                             // 48*256 = 12288 = O_TOT*12

// Merged prologue: [0,2048) transpose x -> g_xt ; [2048,2096) repack params.
__global__ void prep_kernel(const float* __restrict__ x,
                            const float* __restrict__ th,
                            const void*  __restrict__ ord_raw) {
    if (blockIdx.x < TRANS_BLOCKS) {
        __shared__ float t[32][33];
        const int tb = blockIdx.x;
        const int cb = tb & (C_IN / 32 - 1);   // channel tile 0..15
        const int bb = tb >> 4;                // b tile 0..127
        const int lane = threadIdx.x & 31, w = threadIdx.x >> 5;
        #pragma unroll
        for (int r = w; r < 32; r += 8)
            t[r][lane] = x[(size_t)(bb * 32 + r) * C_IN + cb * 32 + lane];
        __syncthreads();
        #pragma unroll
        for (int r = w; r < 32; r += 8)
            g_xt[(size_t)(cb * 32 + r) * B_TOT + bb * 32 + lane] = t[lane][r];
    } else {
        // Detect ordinals dtype (int64 vs int32) by value-range test.
        __shared__ int is64_s;
        if (threadIdx.x == 0) {
            const long long* p = (const long long*)ord_raw;
            int ok = 1;
            for (int i = 0; i < 16; i++) {
                long long v = p[i];
                if (v < 0 || v >= C_IN) ok = 0;
            }
            is64_s = ok;
        }
        __syncthreads();
        const int use64 = is64_s;
        const long long* p64 = (const long long*)ord_raw;
        const int*       p32 = (const int*)ord_raw;
        float* thf = (float*)g_thp;
        int*   odf = (int*)g_ordp;
        int j = (blockIdx.x - TRANS_BLOCKS) * blockDim.x + threadIdx.x;
        if (j < O_TOT * 12) {
            int o = j / 12, k = j % 12;
            float tv = 0.0f;
            int   ov = 0;
            if (k < DD) {
                tv = th[o * DD + k];
                ov = (use64 ? (int)p64[o * DD + k] : p32[o * DD + k]) * B_TOT;
            }
            thf[j] = tv;
            odf[j] = ov;
        }
    }
}

__global__ __launch_bounds__(NTHREADS, 4)
void fern_kernel(const float* __restrict__ wts, float* __restrict__ out) {
    extern __shared__ float sm[];
    float* wsm   = sm;                  // [OT][LL] staged weights (32KB)
    float* stage = sm + W_SM_FLOATS;    // [2][OT][ST_PITCH] ping-pong stage

    const int tid  = threadIdx.x;
    const int lane = tid & 31;
    const int warp = tid >> 5;          // o within CTA (fixed)
    const int o_begin = blockIdx.y * OT;
    const int bbase   = blockIdx.x * B_PER_CTA;

    // Stage weights [o_begin : o_begin+8] into smem. 2048 float4 / 256 thr = 8 each.
    {
        const float4* src = (const float4*)(wts + (size_t)o_begin * LL);
        float4* dst = (float4*)wsm;
        #pragma unroll
        for (int i = 0; i < W_SM_FLOATS / 4 / NTHREADS; i++)
            dst[tid + i * NTHREADS] = src[tid + i * NTHREADS];
    }

    // Per-warp params, loaded ONCE (o fixed for entire CTA lifetime).
    const int o = o_begin + warp;
    const float4 t0 = g_thp[o * 3 + 0];
    const float4 t1 = g_thp[o * 3 + 1];
    const float4 t2 = g_thp[o * 3 + 2];
    const int4   c0 = g_ordp[o * 3 + 0];
    const int4   c1 = g_ordp[o * 3 + 1];
    const int4   c2 = g_ordp[o * 3 + 2];

    // 10 float2 base pointers: each lane covers b = 2*lane, 2*lane+1.
    // (bbase and pre-scaled ordinals are even -> float2-aligned.)
    const float* xf = g_xt + bbase;
    const float2* xp0 = (const float2*)(xf + c0.x) + lane;
    const float2* xp1 = (const float2*)(xf + c0.y) + lane;
    const float2* xp2 = (const float2*)(xf + c0.z) + lane;
    const float2* xp3 = (const float2*)(xf + c0.w) + lane;
    const float2* xp4 = (const float2*)(xf + c1.x) + lane;
    const float2* xp5 = (const float2*)(xf + c1.y) + lane;
    const float2* xp6 = (const float2*)(xf + c1.z) + lane;
    const float2* xp7 = (const float2*)(xf + c1.w) + lane;
    const float2* xp8 = (const float2*)(xf + c2.x) + lane;
    const float2* xp9 = (const float2*)(xf + c2.y) + lane;
    const float* wrow = wsm + (warp << 10);

    __syncthreads();   // weights staged

    #pragma unroll
    for (int itp = 0; itp < B_PER_CTA / 64; itp++) {     // 8 iterations
        float* sbuf = stage + (itp & 1) * (OT * ST_PITCH);
        const int off = itp * 32;                        // float2 elements

        // 10 independent coalesced LDG.64 in flight (64 b's this iter).
        float2 v0 = xp0[off];
        float2 v1 = xp1[off];
        float2 v2 = xp2[off];
        float2 v3 = xp3[off];
        float2 v4 = xp4[off];
        float2 v5 = xp5[off];
        float2 v6 = xp6[off];
        float2 v7 = xp7[off];
        float2 v8 = xp8[off];
        float2 v9 = xp9[off];

        float r0, r1;
        {   // b = 2*lane  (.x components)
            float m0 = v0.x - t0.x, m1 = v1.x - t0.y, m2 = v2.x - t0.z;
            float m3 = v3.x - t0.w, m4 = v4.x - t1.x, m5 = v5.x - t1.y;
            float m6 = v6.x - t1.z, m7 = v7.x - t1.w, m8 = v8.x - t2.x;
            float m9 = v9.x - t2.y;
            int leaf = ((m0 > 0.0f) << 9) | ((m1 > 0.0f) << 8) |
                       ((m2 > 0.0f) << 7) | ((m3 > 0.0f) << 6) |
                       ((m4 > 0.0f) << 5) | ((m5 > 0.0f) << 4) |
                       ((m6 > 0.0f) << 3) | ((m7 > 0.0f) << 2) |
                       ((m8 > 0.0f) << 1) |  (m9 > 0.0f);
            float mn = fminf(
                fminf(fminf(fminf(fabsf(m0), fabsf(m1)), fminf(fabsf(m2), fabsf(m3))),
                      fminf(fminf(fabsf(m4), fabsf(m5)), fminf(fabsf(m6), fabsf(m7)))),
                fminf(fabsf(m8), fabsf(m9)));
            r0 = wrow[leaf] * mn;
        }
        {   // b = 2*lane + 1  (.y components)
            float m0 = v0.y - t0.x, m1 = v1.y - t0.y, m2 = v2.y - t0.z;
            float m3 = v3.y - t0.w, m4 = v4.y - t1.x, m5 = v5.y - t1.y;
            float m6 = v6.y - t1.z, m7 = v7.y - t1.w, m8 = v8.y - t2.x;
            float m9 = v9.y - t2.y;
            int leaf = ((m0 > 0.0f) << 9) | ((m1 > 0.0f) << 8) |
                       ((m2 > 0.0f) << 7) | ((m3 > 0.0f) << 6) |
                       ((m4 > 0.0f) << 5) | ((m5 > 0.0f) << 4) |
                       ((m6 > 0.0f) << 3) | ((m7 > 0.0f) << 2) |
                       ((m8 > 0.0f) << 1) |  (m9 > 0.0f);
            float mn = fminf(
                fminf(fminf(fminf(fabsf(m0), fabsf(m1)), fminf(fabsf(m2), fabsf(m3))),
                      fminf(fminf(fabsf(m4), fabsf(m5)), fminf(fabsf(m6), fabsf(m7)))),
                fminf(fabsf(m8), fabsf(m9)));
            r1 = wrow[leaf] * mn;
        }

        // Stage [o][b]: STS.64 consecutive within the warp -> conflict-free.
        *(float2*)&sbuf[warp * ST_PITCH + 2 * lane] = make_float2(r0, r1);
        __syncthreads();

        // Flush 64 b x 8 o; 2 elements/thread, 32B coalesced STG segments.
        // LDS banks (4*oo + bl) mod 32 with bl in {4w..4w+3}: all 32 distinct
        // per warp -> conflict-free (pitch 68 = 4 mod 32).
        {
            const int bl = tid >> 3, oo = tid & 7;       // bl 0..31, oo 0..7
            const int bg = bbase + itp * 64;
            out[(size_t)(bg + bl) * O_TOT + o_begin + oo] =
                sbuf[oo * ST_PITCH + bl];
            out[(size_t)(bg + bl + 32) * O_TOT + o_begin + oo] =
                sbuf[oo * ST_PITCH + bl + 32];
        }
        // Ping-pong: next iteration writes the other buffer; the next barrier
        // orders reuse of this one. No second barrier needed.
    }
}

extern "C" void kernel_launch(void* const* d_in, const int* in_sizes, int n_in,
                              void* d_out, int out_size) {
    (void)in_sizes; (void)n_in; (void)out_size;
    const float* x   = (const float*)d_in[0];
    const float* th  = (const float*)d_in[1];
    const void*  ord = d_in[2];
    const float* wts = (const float*)d_in[3];
    float* out = (float*)d_out;

    prep_kernel<<<TRANS_BLOCKS + CONV_BLOCKS, 256>>>(x, th, ord);

    cudaFuncSetAttribute(fern_kernel,
                         cudaFuncAttributeMaxDynamicSharedMemorySize, SMEM_BYTES);
    dim3 grid(NB, O_TOT / OT);   // (8, 128)
    fern_kernel<<<grid, NTHREADS, SMEM_BYTES>>>(wts, out);
}